// round 13
// baseline (speedup 1.0000x reference)
#include <cuda_runtime.h>
#include <cstdint>

// SSIM loss, B=64, 1x512x512 fp32, 11x11 box filter, zero padding.
// R12: R11 with the swizzle-addressing bug fixed. The correct identity is
//   swz(4L+q) = swz(4L) ^ q   (XOR -- mask is q-independent, bits disjoint)
// R11 used swz(4L)+q (ADD), permuting columns -> rel_err 3.6e-3.
// Occupancy experiment otherwise unchanged: CHUNK=16, 512 CTAs x 128 thr,
// launch_bounds(128,3) -> 3 CTAs/SM, coalesced cp.async staging.
// Frozen: reg-lean epilogue, paired divides, split chains, f32x2 packing.

typedef unsigned long long u64;

__device__ __forceinline__ u64 pk2(float lo, float hi) {
    u64 r; asm("mov.b64 %0, {%1, %2};" : "=l"(r) : "f"(lo), "f"(hi)); return r;
}
__device__ __forceinline__ void upk2(u64 v, float& lo, float& hi) {
    asm("mov.b64 {%0, %1}, %2;" : "=f"(lo), "=f"(hi) : "l"(v));
}
__device__ __forceinline__ u64 add2(u64 a, u64 b) {
    u64 r; asm("add.rn.f32x2 %0, %1, %2;" : "=l"(r) : "l"(a), "l"(b)); return r;
}
__device__ __forceinline__ u64 mul2(u64 a, u64 b) {
    u64 r; asm("mul.rn.f32x2 %0, %1, %2;" : "=l"(r) : "l"(a), "l"(b)); return r;
}
__device__ __forceinline__ u64 fma2(u64 a, u64 b, u64 c) {
    u64 r; asm("fma.rn.f32x2 %0, %1, %2, %3;" : "=l"(r) : "l"(a), "l"(b), "l"(c)); return r;
}
__device__ __forceinline__ void cp16(uint32_t dst, const void* src) {
    asm volatile("cp.async.cg.shared.global [%0], [%1], 16;" :: "r"(dst), "l"(src));
}
__device__ __forceinline__ void cp_commit() {
    asm volatile("cp.async.commit_group;" ::: "memory");
}
__device__ __forceinline__ void cp_wait0() {
    asm volatile("cp.async.wait_group 0;" ::: "memory");
}
__device__ __forceinline__ int swz(int j) { return j ^ ((j >> 3) & 7); }

namespace {
constexpr int Hh = 512;
constexpr int Ww = 512;
constexpr int Bb = 64;
constexpr int CHUNK = 16;
constexpr int NCHUNK = Hh / CHUNK;           // 32
constexpr int BLK = 128;                     // 4 warps/CTA
constexpr int NCTA = Bb * NCHUNK * 32 / BLK; // 512
constexpr float C1S = 0.0001f * 14641.0f;    // 1.4641
constexpr float C2S = 0.0009f * 14641.0f;    // 13.1769
}

__device__ double g_acc;
__device__ int    g_count;

template<bool TOP, bool BOT>
__device__ __forceinline__ float run_chunk(const float* __restrict__ xw,
                                           const float* __restrict__ yw,
                                           const int row0, const int lane,
                                           float4 (*sb)[128]) {
    const u64 KN1 = pk2(-1.f, -1.f);
    const float lmaskf = (lane == 0)  ? 0.f : 1.f;
    const float rmaskf = (lane == 31) ? 0.f : 1.f;
    const u64 lmask2 = pk2(lmaskf, lmaskf);
    const u64 rmask2 = pk2(rmaskf, rmaskf);
    const int c0 = lane << 4;

    u64 vab[16], vsq[16];
    float vxy[16];
#pragma unroll
    for (int k = 0; k < 16; k++) { vab[k] = 0ull; vsq[k] = 0ull; vxy[k] = 0.f; }

    float acc = 0.f;

    // staging addresses:
    //   write (b,q): sbase + b*2048 + swz(lane+32q)*16
    //   read  (b,q): flat[b*128 + (idx0 ^ q)], idx0 = swz(4*lane)
    const uint32_t sbase = (uint32_t)__cvta_generic_to_shared(&sb[0][0]);
    uint32_t woff[4];
#pragma unroll
    for (int q = 0; q < 4; q++) woff[q] = (uint32_t)(swz(lane + 32 * q) * 16);
    const float4* flat = &sb[0][0];
    const int idx0 = swz(4 * lane);

#define VENT(k, xs, ys) do { float _x=(xs), _y=(ys); u64 _p=pk2(_x,_y); \
    vab[k]=add2(vab[k],_p); vsq[k]=fma2(_p,_p,vsq[k]); vxy[k]=fmaf(_x,_y,vxy[k]); } while(0)
#define VLEA(k, xs, ys) do { float _x=(xs), _y=(ys); u64 _p=pk2(_x,_y); u64 _n=mul2(_p,KN1); \
    vab[k]=add2(vab[k],_n); vsq[k]=fma2(_n,_p,vsq[k]); vxy[k]=fmaf(-_x,_y,vxy[k]); } while(0)
#define ROW_APPLY(OP) \
    OP(0,a0.x,b0.x);  OP(1,a0.y,b0.y);  OP(2,a0.z,b0.z);  OP(3,a0.w,b0.w); \
    OP(4,a1.x,b1.x);  OP(5,a1.y,b1.y);  OP(6,a1.z,b1.z);  OP(7,a1.w,b1.w); \
    OP(8,a2.x,b2.x);  OP(9,a2.y,b2.y);  OP(10,a2.z,b2.z); OP(11,a2.w,b2.w); \
    OP(12,a3.x,b3.x); OP(13,a3.y,b3.y); OP(14,a3.z,b3.z); OP(15,a3.w,b3.w);

#define ENTER_DIRECT(r) do { \
    const float4* xr = reinterpret_cast<const float4*>(xw + (r) * Ww + c0); \
    const float4* yr = reinterpret_cast<const float4*>(yw + (r) * Ww + c0); \
    float4 a0 = xr[0], a1 = xr[1], a2 = xr[2], a3 = xr[3]; \
    float4 b0 = yr[0], b1 = yr[1], b2 = yr[2], b3 = yr[3]; \
    ROW_APPLY(VENT) } while(0)

#define STAGE(er, lr) do { \
    const float* _ex = xw + (er) * Ww; \
    const float* _ey = yw + (er) * Ww; \
    const float* _lx = xw + (lr) * Ww; \
    const float* _ly = yw + (lr) * Ww; \
    _Pragma("unroll") \
    for (int q = 0; q < 4; q++) { \
        const int w4 = (lane + 32 * q) * 4; \
        cp16(sbase + woff[q],          _ex + w4); \
        cp16(sbase + 2048 + woff[q],   _ey + w4); \
        cp16(sbase + 4096 + woff[q],   _lx + w4); \
        cp16(sbase + 6144 + woff[q],   _ly + w4); \
    } \
    cp_commit(); } while(0)

#define SC4(v, m) do { (v).x*=(m); (v).y*=(m); (v).z*=(m); (v).w*=(m); } while(0)

#define SUM11P(V) add2(add2(add2(add2(V[3],V[4]), add2(V[5],V[6])), \
                            add2(add2(V[7],V[8]), add2(V[9],V[10]))), \
                       add2(add2(V[11],V[12]), V[13]))

#define ND(sab, ssq, sxy, nv, dv) do { \
    float sx, sy, sxx, syy; \
    upk2(sab, sx, sy); \
    upk2(ssq, sxx, syy); \
    float pxy  = sx * sy; \
    float m2   = fmaf(sx, sx, sy * sy); \
    float esum = sxx + syy; \
    nv = fmaf(2.f, pxy, C1S) * fmaf(242.f, sxy, fmaf(-2.f, pxy, C2S)); \
    dv = (m2 + C1S) * fmaf(121.f, esum, C2S - m2); } while(0)

#define EPI() do { \
    u64 hsum_ab = add2(add2(add2(vab[11], vab[12]), add2(vab[13], vab[14])), vab[15]); \
    u64 hsum_sq = add2(add2(add2(vsq[11], vsq[12]), add2(vsq[13], vsq[14])), vsq[15]); \
    float hsum_xy = ((vxy[11] + vxy[12]) + (vxy[13] + vxy[14])) + vxy[15]; \
    u64 sabA = add2(mul2(__shfl_up_sync(0xffffffffu, hsum_ab, 1), lmask2), \
                    add2(add2(add2(vab[0], vab[1]), add2(vab[2], vab[3])), add2(vab[4], vab[5]))); \
    u64 ssqA = add2(mul2(__shfl_up_sync(0xffffffffu, hsum_sq, 1), lmask2), \
                    add2(add2(add2(vsq[0], vsq[1]), add2(vsq[2], vsq[3])), add2(vsq[4], vsq[5]))); \
    float sxyA = __shfl_up_sync(0xffffffffu, hsum_xy, 1) * lmaskf \
               + (((vxy[0] + vxy[1]) + (vxy[2] + vxy[3])) + (vxy[4] + vxy[5])); \
    u64 sabB = SUM11P(vab); \
    u64 ssqB = SUM11P(vsq); \
    float sxyB = ((vxy[3]+vxy[4]) + (vxy[5]+vxy[6])) + ((vxy[7]+vxy[8]) + (vxy[9]+vxy[10])) \
               + ((vxy[11]+vxy[12]) + vxy[13]); \
    _Pragma("unroll") \
    for (int j = 0; j < 8; j++) { \
        float nA, dA, nB, dB; \
        ND(sabA, ssqA, sxyA, nA, dA); \
        ND(sabB, ssqB, sxyB, nB, dB); \
        acc += __fdividef(fmaf(nA, dB, nB * dA), dA * dB); \
        if (j < 7) { \
            sabA = add2(sabA, vab[j + 6]); \
            ssqA = add2(ssqA, vsq[j + 6]); \
            sxyA += vxy[j + 6]; \
            if (j < 5) { \
                u64 ha = mul2(__shfl_up_sync(0xffffffffu, vab[11 + j], 1), lmask2); \
                u64 hs = mul2(__shfl_up_sync(0xffffffffu, vsq[11 + j], 1), lmask2); \
                float hx = __shfl_up_sync(0xffffffffu, vxy[11 + j], 1) * lmaskf; \
                sabA = fma2(ha, KN1, sabA); \
                ssqA = fma2(hs, KN1, ssqA); \
                sxyA -= hx; \
            } else { \
                sabA = fma2(vab[j - 5], KN1, sabA); \
                ssqA = fma2(vsq[j - 5], KN1, ssqA); \
                sxyA -= vxy[j - 5]; \
            } \
            u64 hb_ab, hb_sq; \
            float hb_xy; \
            if (j < 2) { \
                hb_ab = vab[14 + j]; hb_sq = vsq[14 + j]; hb_xy = vxy[14 + j]; \
            } else { \
                hb_ab = mul2(__shfl_down_sync(0xffffffffu, vab[j - 2], 1), rmask2); \
                hb_sq = mul2(__shfl_down_sync(0xffffffffu, vsq[j - 2], 1), rmask2); \
                hb_xy = __shfl_down_sync(0xffffffffu, vxy[j - 2], 1) * rmaskf; \
            } \
            sabB = add2(sabB, hb_ab); \
            sabB = fma2(vab[j + 3], KN1, sabB); \
            ssqB = add2(ssqB, hb_sq); \
            ssqB = fma2(vsq[j + 3], KN1, ssqB); \
            sxyB += hb_xy - vxy[j + 3]; \
        } \
    } } while(0)

    // ---- warmup: rows row0-5 .. row0+4 (direct loads) ----
    {
        const int w0 = TOP ? 5 : 0;
#pragma unroll
        for (int i = w0; i < 10; i++) ENTER_DIRECT(row0 - 5 + i);
    }

    // ---- first output row (ri = row0+5, no leave) ----
    ENTER_DIRECT(row0 + 5);
    {   // stage iter-0 rows
        const int er = row0 + 6;
        const int lr = TOP ? 0 : (row0 - 5);
        STAGE(er, lr);
    }
    EPI();

    // ---- steady: CHUNK-1 iterations, depth-1 pipeline ----
#pragma unroll 1
    for (int i = 0; i < CHUNK - 1; i++) {
        const int ri = row0 + 6 + i;
        const int lv = ri - 11;
        cp_wait0();
        __syncwarp();
        {   // consume enter  (read index = idx0 ^ q, NOT idx0 + q)
            float4 a0 = flat[idx0 ^ 0], a1 = flat[idx0 ^ 1],
                   a2 = flat[idx0 ^ 2], a3 = flat[idx0 ^ 3];
            float4 b0 = flat[128 + (idx0 ^ 0)], b1 = flat[128 + (idx0 ^ 1)],
                   b2 = flat[128 + (idx0 ^ 2)], b3 = flat[128 + (idx0 ^ 3)];
            if (BOT) {
                const float em = (ri < Hh) ? 1.f : 0.f;
                SC4(a0, em); SC4(a1, em); SC4(a2, em); SC4(a3, em);
                SC4(b0, em); SC4(b1, em); SC4(b2, em); SC4(b3, em);
            }
            ROW_APPLY(VENT)
        }
        {   // consume leave
            float4 a0 = flat[256 + (idx0 ^ 0)], a1 = flat[256 + (idx0 ^ 1)],
                   a2 = flat[256 + (idx0 ^ 2)], a3 = flat[256 + (idx0 ^ 3)];
            float4 b0 = flat[384 + (idx0 ^ 0)], b1 = flat[384 + (idx0 ^ 1)],
                   b2 = flat[384 + (idx0 ^ 2)], b3 = flat[384 + (idx0 ^ 3)];
            if (TOP) {
                const float lm = (lv >= 0) ? 1.f : 0.f;
                SC4(a0, lm); SC4(a1, lm); SC4(a2, lm); SC4(a3, lm);
                SC4(b0, lm); SC4(b1, lm); SC4(b2, lm); SC4(b3, lm);
            }
            ROW_APPLY(VLEA)
        }
        __syncwarp();
        if (i < CHUNK - 2) {   // stage next iteration's rows (hidden under EPI)
            int er = ri + 1; if (BOT && er > Hh - 1) er = Hh - 1;
            int lr = lv + 1; if (TOP && lr < 0) lr = 0;
            STAGE(er, lr);
        }
        EPI();
    }

    return acc;

#undef VENT
#undef VLEA
#undef ROW_APPLY
#undef ENTER_DIRECT
#undef STAGE
#undef SC4
#undef SUM11P
#undef ND
#undef EPI
}

__global__ void __launch_bounds__(BLK, 3)
k_ssim(const float* __restrict__ X, const float* __restrict__ Y, float* __restrict__ out) {
    const int warp  = threadIdx.x >> 5;
    const int lane  = threadIdx.x & 31;
    const int gwarp = blockIdx.x * (BLK / 32) + warp;
    const int batch = gwarp >> 5;              // / NCHUNK (=32)
    const int chunk = gwarp & (NCHUNK - 1);
    const int row0  = chunk * CHUNK;
    const float* xw = X + batch * (Hh * Ww);
    const float* yw = Y + batch * (Hh * Ww);

    __shared__ float4 sstage[BLK / 32][4][128];   // 32 KB/CTA
    __shared__ float  s_red[BLK / 32];

    float acc;
    if (chunk == 0)                acc = run_chunk<true,  false>(xw, yw, 0,    lane, sstage[warp]);
    else if (chunk == NCHUNK - 1)  acc = run_chunk<false, true >(xw, yw, row0, lane, sstage[warp]);
    else                           acc = run_chunk<false, false>(xw, yw, row0, lane, sstage[warp]);

#pragma unroll
    for (int off = 16; off; off >>= 1)
        acc += __shfl_xor_sync(0xffffffffu, acc, off);
    if (lane == 0) s_red[warp] = acc;
    __syncthreads();
    if (threadIdx.x == 0) {
        float ctot = 0.f;
#pragma unroll
        for (int w = 0; w < BLK / 32; w++) ctot += s_red[w];
        atomicAdd(&g_acc, (double)ctot);
        __threadfence();
        int old = atomicAdd(&g_count, 1);
        if (old == NCTA - 1) {
            double total = g_acc;
            out[0] = (float)(1.0 - total * (1.0 / ((double)Bb * Hh * Ww)));
            g_acc = 0.0;
            g_count = 0;
        }
    }
}

extern "C" void kernel_launch(void* const* d_in, const int* in_sizes, int n_in,
                              void* d_out, int out_size) {
    const float* x = (const float*)d_in[0];
    const float* y = (const float*)d_in[1];
    (void)in_sizes; (void)n_in; (void)out_size;
    k_ssim<<<NCTA, BLK>>>(x, y, (float*)d_out);
}

// round 14
// speedup vs baseline: 1.2368x; 1.2368x over previous
#include <cuda_runtime.h>
#include <cstdint>

// SSIM loss, B=64, 1x512x512 fp32, 11x11 box filter, zero padding.
// R13: halo-free sliding recurrences. R12 killed the occupancy axis for good
// (4th confirmation: more warps regress). Back to the R9 frame (51.9us).
// The epilogue's in-chain shuffles (26cyc SHFL latency embedded in the
// serial slide recurrence at chain A j=0..4 / chain B j>=2) are hoisted:
//   S(j) = T(j) + H(j);  T = pure lane-local lat-4 recurrence;
//   H = lane-1 suffix sums (A, j<5) / lane+1 prefix sums (B, j>=3),
//   built from 30 up-front independent shuffles + off-chain adds.
// Frame frozen: CHUNK=32, 256 CTAs x 128 thr, depth-1 coalesced cp.async
// staging, paired divides, f32x2 packing, last-CTA finalize.

typedef unsigned long long u64;

__device__ __forceinline__ u64 pk2(float lo, float hi) {
    u64 r; asm("mov.b64 %0, {%1, %2};" : "=l"(r) : "f"(lo), "f"(hi)); return r;
}
__device__ __forceinline__ void upk2(u64 v, float& lo, float& hi) {
    asm("mov.b64 {%0, %1}, %2;" : "=f"(lo), "=f"(hi) : "l"(v));
}
__device__ __forceinline__ u64 add2(u64 a, u64 b) {
    u64 r; asm("add.rn.f32x2 %0, %1, %2;" : "=l"(r) : "l"(a), "l"(b)); return r;
}
__device__ __forceinline__ u64 mul2(u64 a, u64 b) {
    u64 r; asm("mul.rn.f32x2 %0, %1, %2;" : "=l"(r) : "l"(a), "l"(b)); return r;
}
__device__ __forceinline__ u64 fma2(u64 a, u64 b, u64 c) {
    u64 r; asm("fma.rn.f32x2 %0, %1, %2, %3;" : "=l"(r) : "l"(a), "l"(b), "l"(c)); return r;
}
__device__ __forceinline__ void cp16(uint32_t dst, const void* src) {
    asm volatile("cp.async.cg.shared.global [%0], [%1], 16;" :: "r"(dst), "l"(src));
}
__device__ __forceinline__ void cp_commit() {
    asm volatile("cp.async.commit_group;" ::: "memory");
}
__device__ __forceinline__ void cp_wait0() {
    asm volatile("cp.async.wait_group 0;" ::: "memory");
}
__device__ __forceinline__ int swz(int j) { return j ^ ((j >> 3) & 7); }

namespace {
constexpr int Hh = 512;
constexpr int Ww = 512;
constexpr int Bb = 64;
constexpr int CHUNK = 32;
constexpr int NCHUNK = Hh / CHUNK;           // 16
constexpr int BLK = 128;                     // 4 warps/CTA
constexpr int NCTA = Bb * NCHUNK * 32 / BLK; // 256
constexpr float C1S = 0.0001f * 14641.0f;    // 1.4641
constexpr float C2S = 0.0009f * 14641.0f;    // 13.1769
}

__device__ double g_acc;
__device__ int    g_count;

template<bool TOP, bool BOT>
__device__ __forceinline__ float run_chunk(const float* __restrict__ xw,
                                           const float* __restrict__ yw,
                                           const int row0, const int lane,
                                           float4 (*sb)[128]) {
    const u64 KN1 = pk2(-1.f, -1.f);
    const float lmaskf = (lane == 0)  ? 0.f : 1.f;
    const float rmaskf = (lane == 31) ? 0.f : 1.f;
    const u64 lmask2 = pk2(lmaskf, lmaskf);
    const u64 rmask2 = pk2(rmaskf, rmaskf);
    const int c0 = lane << 4;

    u64 vab[16], vsq[16];
    float vxy[16];
#pragma unroll
    for (int k = 0; k < 16; k++) { vab[k] = 0ull; vsq[k] = 0ull; vxy[k] = 0.f; }

    float acc = 0.f;

    // staging addresses: write (b,q) -> sbase + b*2048 + swz(lane+32q)*16
    //                    read  (b,q) -> flat[b*128 + (idx0 ^ q)]
    const uint32_t sbase = (uint32_t)__cvta_generic_to_shared(&sb[0][0]);
    uint32_t woff[4];
#pragma unroll
    for (int q = 0; q < 4; q++) woff[q] = (uint32_t)(swz(lane + 32 * q) * 16);
    const float4* flat = &sb[0][0];
    const int idx0 = swz(4 * lane);

#define VENT(k, xs, ys) do { float _x=(xs), _y=(ys); u64 _p=pk2(_x,_y); \
    vab[k]=add2(vab[k],_p); vsq[k]=fma2(_p,_p,vsq[k]); vxy[k]=fmaf(_x,_y,vxy[k]); } while(0)
#define VLEA(k, xs, ys) do { float _x=(xs), _y=(ys); u64 _p=pk2(_x,_y); u64 _n=mul2(_p,KN1); \
    vab[k]=add2(vab[k],_n); vsq[k]=fma2(_n,_p,vsq[k]); vxy[k]=fmaf(-_x,_y,vxy[k]); } while(0)
#define ROW_APPLY(OP) \
    OP(0,a0.x,b0.x);  OP(1,a0.y,b0.y);  OP(2,a0.z,b0.z);  OP(3,a0.w,b0.w); \
    OP(4,a1.x,b1.x);  OP(5,a1.y,b1.y);  OP(6,a1.z,b1.z);  OP(7,a1.w,b1.w); \
    OP(8,a2.x,b2.x);  OP(9,a2.y,b2.y);  OP(10,a2.z,b2.z); OP(11,a2.w,b2.w); \
    OP(12,a3.x,b3.x); OP(13,a3.y,b3.y); OP(14,a3.z,b3.z); OP(15,a3.w,b3.w);

#define ENTER_DIRECT(r) do { \
    const float4* xr = reinterpret_cast<const float4*>(xw + (r) * Ww + c0); \
    const float4* yr = reinterpret_cast<const float4*>(yw + (r) * Ww + c0); \
    float4 a0 = xr[0], a1 = xr[1], a2 = xr[2], a3 = xr[3]; \
    float4 b0 = yr[0], b1 = yr[1], b2 = yr[2], b3 = yr[3]; \
    ROW_APPLY(VENT) } while(0)

#define STAGE(er, lr) do { \
    const float* _ex = xw + (er) * Ww; \
    const float* _ey = yw + (er) * Ww; \
    const float* _lx = xw + (lr) * Ww; \
    const float* _ly = yw + (lr) * Ww; \
    _Pragma("unroll") \
    for (int q = 0; q < 4; q++) { \
        const int w4 = (lane + 32 * q) * 4; \
        cp16(sbase + woff[q],          _ex + w4); \
        cp16(sbase + 2048 + woff[q],   _ey + w4); \
        cp16(sbase + 4096 + woff[q],   _lx + w4); \
        cp16(sbase + 6144 + woff[q],   _ly + w4); \
    } \
    cp_commit(); } while(0)

#define SC4(v, m) do { (v).x*=(m); (v).y*=(m); (v).z*=(m); (v).w*=(m); } while(0)

#define SUM11P(V) add2(add2(add2(add2(V[3],V[4]), add2(V[5],V[6])), \
                            add2(add2(V[7],V[8]), add2(V[9],V[10]))), \
                       add2(add2(V[11],V[12]), V[13]))

#define ND(sab, ssq, sxy, nv, dv) do { \
    float sx, sy, sxx, syy; \
    upk2(sab, sx, sy); \
    upk2(ssq, sxx, syy); \
    float pxy  = sx * sy; \
    float m2   = fmaf(sx, sx, sy * sy); \
    float esum = sxx + syy; \
    nv = fmaf(2.f, pxy, C1S) * fmaf(242.f, sxy, fmaf(-2.f, pxy, C2S)); \
    dv = (m2 + C1S) * fmaf(121.f, esum, C2S - m2); } while(0)

    // ---- epilogue: halo-free recurrences, all shuffles hoisted ----
    // chain A (cols 0..7):  SA(j) = TA(j) + (j<5 ? Lsuf[j] : 0)
    //   TA(0)=sum v[0..5];  TA(j+1)=TA(j)+v[j+6]  (-v[j-5] when j>=5)
    //   Lsuf[j] = lane-1 sum v[11+j..15]  (suffix sums of masked shuffles)
    // chain B (cols 8..15): SB(j) = TB(j) + (j>=3 ? Rpre[j-3] : 0)
    //   TB(0)=sum v[3..13]; TB(j+1)=TB(j)-v[j+3]  (+v[14+j] when j<2)
    //   Rpre[k] = lane+1 sum v[0..k]      (prefix sums of masked shuffles)
#define EPI() do { \
    u64 Lab[5], Lsq[5], Rab[5], Rsq[5]; \
    float Lxy[5], Rxy[5]; \
    _Pragma("unroll") \
    for (int j = 0; j < 5; j++) { \
        Lab[j] = mul2(__shfl_up_sync(0xffffffffu, vab[11 + j], 1), lmask2); \
        Lsq[j] = mul2(__shfl_up_sync(0xffffffffu, vsq[11 + j], 1), lmask2); \
        Lxy[j] = __shfl_up_sync(0xffffffffu, vxy[11 + j], 1) * lmaskf; \
        Rab[j] = mul2(__shfl_down_sync(0xffffffffu, vab[j], 1), rmask2); \
        Rsq[j] = mul2(__shfl_down_sync(0xffffffffu, vsq[j], 1), rmask2); \
        Rxy[j] = __shfl_down_sync(0xffffffffu, vxy[j], 1) * rmaskf; \
    } \
    _Pragma("unroll") \
    for (int j = 3; j >= 0; j--) {            /* suffix sums */ \
        Lab[j] = add2(Lab[j], Lab[j + 1]); \
        Lsq[j] = add2(Lsq[j], Lsq[j + 1]); \
        Lxy[j] += Lxy[j + 1]; \
    } \
    _Pragma("unroll") \
    for (int j = 1; j < 5; j++) {             /* prefix sums */ \
        Rab[j] = add2(Rab[j], Rab[j - 1]); \
        Rsq[j] = add2(Rsq[j], Rsq[j - 1]); \
        Rxy[j] += Rxy[j - 1]; \
    } \
    u64 taab = add2(add2(add2(vab[0], vab[1]), add2(vab[2], vab[3])), add2(vab[4], vab[5])); \
    u64 tasq = add2(add2(add2(vsq[0], vsq[1]), add2(vsq[2], vsq[3])), add2(vsq[4], vsq[5])); \
    float taxy = ((vxy[0] + vxy[1]) + (vxy[2] + vxy[3])) + (vxy[4] + vxy[5]); \
    u64 tbab = SUM11P(vab); \
    u64 tbsq = SUM11P(vsq); \
    float tbxy = ((vxy[3]+vxy[4]) + (vxy[5]+vxy[6])) + ((vxy[7]+vxy[8]) + (vxy[9]+vxy[10])) \
               + ((vxy[11]+vxy[12]) + vxy[13]); \
    _Pragma("unroll") \
    for (int j = 0; j < 8; j++) { \
        u64 sabA   = (j < 5) ? add2(taab, Lab[j]) : taab; \
        u64 ssqA   = (j < 5) ? add2(tasq, Lsq[j]) : tasq; \
        float sxyA = (j < 5) ? (taxy + Lxy[j]) : taxy; \
        u64 sabB   = (j >= 3) ? add2(tbab, Rab[j - 3]) : tbab; \
        u64 ssqB   = (j >= 3) ? add2(tbsq, Rsq[j - 3]) : tbsq; \
        float sxyB = (j >= 3) ? (tbxy + Rxy[j - 3]) : tbxy; \
        float nA, dA, nB, dB; \
        ND(sabA, ssqA, sxyA, nA, dA); \
        ND(sabB, ssqB, sxyB, nB, dB); \
        acc += __fdividef(fmaf(nA, dB, nB * dA), dA * dB); \
        if (j < 7) { \
            taab = add2(taab, vab[j + 6]); \
            tasq = add2(tasq, vsq[j + 6]); \
            taxy += vxy[j + 6]; \
            if (j >= 5) { \
                taab = fma2(vab[j - 5], KN1, taab); \
                tasq = fma2(vsq[j - 5], KN1, tasq); \
                taxy -= vxy[j - 5]; \
            } \
            tbab = fma2(vab[j + 3], KN1, tbab); \
            tbsq = fma2(vsq[j + 3], KN1, tbsq); \
            tbxy -= vxy[j + 3]; \
            if (j < 2) { \
                tbab = add2(tbab, vab[14 + j]); \
                tbsq = add2(tbsq, vsq[14 + j]); \
                tbxy += vxy[14 + j]; \
            } \
        } \
    } } while(0)

    // ---- warmup: rows row0-5 .. row0+4 (direct loads) ----
    {
        const int w0 = TOP ? 5 : 0;
#pragma unroll
        for (int i = w0; i < 10; i++) ENTER_DIRECT(row0 - 5 + i);
    }

    // ---- first output row (ri = row0+5, no leave) ----
    ENTER_DIRECT(row0 + 5);
    {   // stage iter-0 rows
        const int er = row0 + 6;
        const int lr = TOP ? 0 : (row0 - 5);
        STAGE(er, lr);
    }
    EPI();

    // ---- steady: 31 iterations, depth-1 pipeline ----
#pragma unroll 1
    for (int i = 0; i < CHUNK - 1; i++) {
        const int ri = row0 + 6 + i;
        const int lv = ri - 11;
        cp_wait0();
        __syncwarp();
        {   // consume enter  (read index = idx0 ^ q)
            float4 a0 = flat[idx0 ^ 0], a1 = flat[idx0 ^ 1],
                   a2 = flat[idx0 ^ 2], a3 = flat[idx0 ^ 3];
            float4 b0 = flat[128 + (idx0 ^ 0)], b1 = flat[128 + (idx0 ^ 1)],
                   b2 = flat[128 + (idx0 ^ 2)], b3 = flat[128 + (idx0 ^ 3)];
            if (BOT) {
                const float em = (ri < Hh) ? 1.f : 0.f;
                SC4(a0, em); SC4(a1, em); SC4(a2, em); SC4(a3, em);
                SC4(b0, em); SC4(b1, em); SC4(b2, em); SC4(b3, em);
            }
            ROW_APPLY(VENT)
        }
        {   // consume leave
            float4 a0 = flat[256 + (idx0 ^ 0)], a1 = flat[256 + (idx0 ^ 1)],
                   a2 = flat[256 + (idx0 ^ 2)], a3 = flat[256 + (idx0 ^ 3)];
            float4 b0 = flat[384 + (idx0 ^ 0)], b1 = flat[384 + (idx0 ^ 1)],
                   b2 = flat[384 + (idx0 ^ 2)], b3 = flat[384 + (idx0 ^ 3)];
            if (TOP) {
                const float lm = (lv >= 0) ? 1.f : 0.f;
                SC4(a0, lm); SC4(a1, lm); SC4(a2, lm); SC4(a3, lm);
                SC4(b0, lm); SC4(b1, lm); SC4(b2, lm); SC4(b3, lm);
            }
            ROW_APPLY(VLEA)
        }
        __syncwarp();
        if (i < CHUNK - 2) {   // stage next iteration's rows (hidden under EPI)
            int er = ri + 1; if (BOT && er > Hh - 1) er = Hh - 1;
            int lr = lv + 1; if (TOP && lr < 0) lr = 0;
            STAGE(er, lr);
        }
        EPI();
    }

    return acc;

#undef VENT
#undef VLEA
#undef ROW_APPLY
#undef ENTER_DIRECT
#undef STAGE
#undef SC4
#undef SUM11P
#undef ND
#undef EPI
}

__global__ void __launch_bounds__(BLK)
k_ssim(const float* __restrict__ X, const float* __restrict__ Y, float* __restrict__ out) {
    const int warp  = threadIdx.x >> 5;
    const int lane  = threadIdx.x & 31;
    const int gwarp = blockIdx.x * (BLK / 32) + warp;
    const int batch = gwarp >> 4;              // / NCHUNK
    const int chunk = gwarp & (NCHUNK - 1);
    const int row0  = chunk * CHUNK;
    const float* xw = X + batch * (Hh * Ww);
    const float* yw = Y + batch * (Hh * Ww);

    __shared__ float4 sstage[BLK / 32][4][128];   // 32 KB/CTA
    __shared__ float  s_red[BLK / 32];

    float acc;
    if (chunk == 0)                acc = run_chunk<true,  false>(xw, yw, 0,    lane, sstage[warp]);
    else if (chunk == NCHUNK - 1)  acc = run_chunk<false, true >(xw, yw, row0, lane, sstage[warp]);
    else                           acc = run_chunk<false, false>(xw, yw, row0, lane, sstage[warp]);

#pragma unroll
    for (int off = 16; off; off >>= 1)
        acc += __shfl_xor_sync(0xffffffffu, acc, off);
    if (lane == 0) s_red[warp] = acc;
    __syncthreads();
    if (threadIdx.x == 0) {
        float ctot = 0.f;
#pragma unroll
        for (int w = 0; w < BLK / 32; w++) ctot += s_red[w];
        atomicAdd(&g_acc, (double)ctot);
        __threadfence();
        int old = atomicAdd(&g_count, 1);
        if (old == NCTA - 1) {
            double total = g_acc;
            out[0] = (float)(1.0 - total * (1.0 / ((double)Bb * Hh * Ww)));
            g_acc = 0.0;
            g_count = 0;
        }
    }
}

extern "C" void kernel_launch(void* const* d_in, const int* in_sizes, int n_in,
                              void* d_out, int out_size) {
    const float* x = (const float*)d_in[0];
    const float* y = (const float*)d_in[1];
    (void)in_sizes; (void)n_in; (void)out_size;
    k_ssim<<<NCTA, BLK>>>(x, y, (float*)d_out);
}